// round 12
// baseline (speedup 1.0000x reference)
#include <cuda_runtime.h>
#include <cuda_bf16.h>
#include <math.h>
#include <stdint.h>

#define NTOK 16384
#define KDIM 768
#define KHID 3072
#define NEXP 5

// ---------------- device scratch (static, allocation-free) ----------------
__device__ int   g_count[NEXP];
__device__ int   g_tok[NEXP * NTOK];
__device__ float g_gate[NEXP * NTOK];
__device__ float g_H[(size_t)NTOK * KHID];   // fp32 hidden scratch

// ---------------- helpers ----------------
__device__ __forceinline__ uint32_t smem_u32(const void* p) {
    uint32_t a;
    asm("{ .reg .u64 t; cvta.to.shared.u64 t, %1; cvt.u32.u64 %0, t; }" : "=r"(a) : "l"(p));
    return a;
}
__device__ __forceinline__ void mma16816(float (&c)[4], const uint32_t (&a)[4],
                                         uint32_t b0, uint32_t b1) {
    asm volatile("mma.sync.aligned.m16n8k16.row.col.f32.bf16.bf16.f32 "
                 "{%0,%1,%2,%3}, {%4,%5,%6,%7}, {%8,%9}, {%0,%1,%2,%3};"
                 : "+f"(c[0]), "+f"(c[1]), "+f"(c[2]), "+f"(c[3])
                 : "r"(a[0]), "r"(a[1]), "r"(a[2]), "r"(a[3]), "r"(b0), "r"(b1));
}
__device__ __forceinline__ void ldsm4(uint32_t (&d)[4], uint32_t addr) {
    asm volatile("ldmatrix.sync.aligned.m8n8.x4.shared.b16 {%0,%1,%2,%3}, [%4];"
                 : "=r"(d[0]), "=r"(d[1]), "=r"(d[2]), "=r"(d[3]) : "r"(addr));
}
__device__ __forceinline__ void ldsm4t(uint32_t (&d)[4], uint32_t addr) {
    asm volatile("ldmatrix.sync.aligned.m8n8.x4.trans.shared.b16 {%0,%1,%2,%3}, [%4];"
                 : "=r"(d[0]), "=r"(d[1]), "=r"(d[2]), "=r"(d[3]) : "r"(addr));
}
// split (fx, fy) -> packed bf16x2 hi (fx in low half) and bf16x2 lo (residual)
__device__ __forceinline__ void split2(float fx, float fy, uint32_t& hi, uint32_t& lo) {
    uint32_t h;
    asm("cvt.rn.bf16x2.f32 %0, %1, %2;" : "=r"(h) : "f"(fy), "f"(fx));
    float lx = fx - __uint_as_float(h << 16);
    float ly = fy - __uint_as_float(h & 0xffff0000u);
    asm("cvt.rn.bf16x2.f32 %0, %1, %2;" : "=r"(lo) : "f"(ly), "f"(lx));
    hi = h;
}
__device__ __forceinline__ float gelu_erf(float v) {
    return 0.5f * v * (1.0f + erff(v * 0.70710678118654752f));
}

// ---------------------------------------------------------------------------
__global__ void zero_counts_kernel() {
    if (threadIdx.x < NEXP) g_count[threadIdx.x] = 0;
}

__global__ void gating_kernel(const float* __restrict__ x, const float* __restrict__ wg) {
    int t = (blockIdx.x * blockDim.x + threadIdx.x) >> 5;
    int lane = threadIdx.x & 31;
    if (t >= NTOK) return;
    const float* xr = x + (size_t)t * KDIM;
    float p0 = 0.f, p1 = 0.f, p2 = 0.f, p3 = 0.f, p4 = 0.f;
    for (int k = lane; k < KDIM; k += 32) {
        float xv = xr[k];
        const float* w = wg + (size_t)k * NEXP;
        p0 += xv * w[0]; p1 += xv * w[1]; p2 += xv * w[2]; p3 += xv * w[3]; p4 += xv * w[4];
    }
#pragma unroll
    for (int o = 16; o > 0; o >>= 1) {
        p0 += __shfl_down_sync(0xffffffffu, p0, o);
        p1 += __shfl_down_sync(0xffffffffu, p1, o);
        p2 += __shfl_down_sync(0xffffffffu, p2, o);
        p3 += __shfl_down_sync(0xffffffffu, p3, o);
        p4 += __shfl_down_sync(0xffffffffu, p4, o);
    }
    if (lane == 0) {
        float v[NEXP] = {p0, p1, p2, p3, p4};
        int i0 = 0; float v0 = v[0];
#pragma unroll
        for (int e = 1; e < NEXP; e++) if (v[e] > v0) { v0 = v[e]; i0 = e; }
        int i1 = -1; float v1 = -3.4e38f;
#pragma unroll
        for (int e = 0; e < NEXP; e++) if (e != i0 && v[e] > v1) { v1 = v[e]; i1 = e; }
        float e1 = expf(v1 - v0);
        float s = 1.0f + e1;
        int q0 = atomicAdd(&g_count[i0], 1);
        g_tok[i0 * NTOK + q0] = t;  g_gate[i0 * NTOK + q0] = 1.0f / s;
        int q1 = atomicAdd(&g_count[i1], 1);
        g_tok[i1 * NTOK + q1] = t;  g_gate[i1 * NTOK + q1] = e1 / s;
    }
}

// ---------------------------------------------------------------------------
// GEMM: 128x128 CTA tile, 256 threads, 8 warps (4x2), warp tile 32x64.
// Pre-split fp32 -> bf16 hi/lo at STS into ldmatrix-friendly SMEM.
// DEEP PIPELINE: 2 register staging buffers + 3-stage SMEM ring. LDG(c+2) is
// issued at iter c and consumed by STS at end of iter c+1 -> ~2 chunks of
// compute cover global-load latency.
#define CKE 16
#define ASTR 80
#define BSTR 528
#define A_STAGE (128 * ASTR)   // 10240 B
#define B_STAGE (16 * BSTR)    // 8448 B

// MODE 0 (fc1): A = gathered x rows [*,768], B = W1[e] [768,3072]; epi: g_H = gelu(acc+b1)
// MODE 1 (fc2): A = g_H [*,3072],          B = W2[e] [3072,768]; epi: out[tok] += gate*exp(acc+b2)
template <int MODE>
__global__ __launch_bounds__(256, 1)
void moe_mma_kernel(const float* __restrict__ x, const float* __restrict__ W,
                    const float* __restrict__ bias, int e, float* __restrict__ out) {
    int cnt = g_count[e];
    int row0 = blockIdx.y * 128;
    if (row0 >= cnt) return;
    int col0 = blockIdx.x * 128;

    const int KE = (MODE == 0) ? KDIM : KHID;   // reduction length
    const int NB = (MODE == 0) ? KHID : KDIM;   // output width (B row stride)

    __shared__ __align__(16) char sAbuf[3 * A_STAGE];
    __shared__ __align__(16) char sBbuf[3 * B_STAGE];
    __shared__ float s_bias[128];

    uint32_t Abase = smem_u32(sAbuf);
    uint32_t Bbase = smem_u32(sBbuf);

    int tid = threadIdx.x, wid = tid >> 5, lane = tid & 31;
    int wm = (wid & 3) * 32, wn = (wid >> 2) * 64;   // 4x2 warp grid, 32x64 tiles
    int g = lane >> 2, t4 = lane & 3;

    if (tid < 128) s_bias[tid] = bias[(size_t)e * NB + col0 + tid];

    // ---- per-lane ldmatrix base addresses (within stage 0) ----
    int mi = lane >> 3, rr = lane & 7;
    uint32_t aAddr = Abase + (uint32_t)((wm + ((mi & 1) << 3) + rr) * ASTR + ((mi >> 1) << 4));
    uint32_t bAddr = Bbase + (uint32_t)((((mi & 1) << 3) + rr) * BSTR + (wn + ((mi >> 1) << 3)) * 2);

    // ---- A loader: thread -> quad q (k 4q..4q+3), rows r0 and r0+64 ----
    int q = tid & 3, r0 = tid >> 2;
    const float *aSrc0, *aSrc1;
    if (MODE == 0) {
        int ga0 = row0 + r0, ga1 = row0 + r0 + 64;
        int tok0 = g_tok[e * NTOK + (ga0 < cnt ? ga0 : row0)];
        int tok1 = g_tok[e * NTOK + (ga1 < cnt ? ga1 : row0)];
        aSrc0 = x + (size_t)tok0 * KDIM + q * 4;
        aSrc1 = x + (size_t)tok1 * KDIM + q * 4;
    } else {
        aSrc0 = g_H + (size_t)(row0 + r0) * KHID + q * 4;       // rows >= cnt: finite garbage
        aSrc1 = g_H + (size_t)(row0 + r0 + 64) * KHID + q * 4;
    }
    // ---- B loader: thread -> k-row kr, n segment seg (8 cols) ----
    int kr = tid >> 4, seg = tid & 15;
    const float* bSrc = W + (size_t)e * KDIM * KHID + (size_t)kr * NB + col0 + seg * 8;

    // two register staging buffers
    float4 vA0[2], vA1[2], vB0[2], vB1[2];
    auto ldg = [&](int c, int rb) {
        vA0[rb] = *(const float4*)(aSrc0 + c * CKE);
        vA1[rb] = *(const float4*)(aSrc1 + c * CKE);
        const float* bp = bSrc + (size_t)c * CKE * NB;
        vB0[rb] = *(const float4*)bp;
        vB1[rb] = *(const float4*)(bp + 4);
    };
    auto sts = [&](int s, int rb) {
        char* Ab = sAbuf + s * A_STAGE;
        char* Bb = sBbuf + s * B_STAGE;
        uint32_t h0, l0, h1, l1, h2, l2, h3, l3;
        split2(vA0[rb].x, vA0[rb].y, h0, l0); split2(vA0[rb].z, vA0[rb].w, h1, l1);
        *(uint2*)(Ab + r0 * ASTR + q * 8)      = make_uint2(h0, h1);
        *(uint2*)(Ab + r0 * ASTR + 32 + q * 8) = make_uint2(l0, l1);
        split2(vA1[rb].x, vA1[rb].y, h0, l0); split2(vA1[rb].z, vA1[rb].w, h1, l1);
        *(uint2*)(Ab + (r0 + 64) * ASTR + q * 8)      = make_uint2(h0, h1);
        *(uint2*)(Ab + (r0 + 64) * ASTR + 32 + q * 8) = make_uint2(l0, l1);
        split2(vB0[rb].x, vB0[rb].y, h0, l0); split2(vB0[rb].z, vB0[rb].w, h1, l1);
        split2(vB1[rb].x, vB1[rb].y, h2, l2); split2(vB1[rb].z, vB1[rb].w, h3, l3);
        *(uint4*)(Bb + kr * BSTR + seg * 16)       = make_uint4(h0, h1, h2, h3);
        *(uint4*)(Bb + kr * BSTR + 256 + seg * 16) = make_uint4(l0, l1, l2, l3);
    };

    float acc[2][8][4];
#pragma unroll
    for (int i = 0; i < 2; i++)
#pragma unroll
        for (int j = 0; j < 8; j++)
#pragma unroll
            for (int k = 0; k < 4; k++) acc[i][j][k] = 0.f;

    const int NC = KE / CKE;
    // prologue: chunk j lives in register buffer j%2, SMEM stage j%3
    ldg(0, 0);
    ldg(1, 1);
    sts(0, 0);

    // stage offsets mod 3
    int st = 0;                 // stage of chunk c
    for (int c = 0; c < NC; c++) {
        __syncthreads();                         // stage st (chunk c) visible
        if (c + 2 < NC) ldg(c + 2, c & 1);       // buffer (c+2)%2 == c%2 (freed by sts at iter c-1)

        uint32_t stA = aAddr + st * A_STAGE;
        uint32_t stB = bAddr + st * B_STAGE;

        uint32_t ah[2][4], al[2][4], bh[4][4], bl[4][4];
#pragma unroll
        for (int mt = 0; mt < 2; mt++) {
            ldsm4(ah[mt], stA + mt * (16 * ASTR));
            ldsm4(al[mt], stA + mt * (16 * ASTR) + 32);
        }
#pragma unroll
        for (int np = 0; np < 4; np++) {
            ldsm4t(bh[np], stB + np * 32);
            ldsm4t(bl[np], stB + np * 32 + 256);
        }

#pragma unroll
        for (int np = 0; np < 4; np++)
#pragma unroll
            for (int mt = 0; mt < 2; mt++) {
                mma16816(acc[mt][np * 2 + 0], ah[mt], bh[np][0], bh[np][1]);
                mma16816(acc[mt][np * 2 + 1], ah[mt], bh[np][2], bh[np][3]);
            }
#pragma unroll
        for (int np = 0; np < 4; np++)
#pragma unroll
            for (int mt = 0; mt < 2; mt++) {
                mma16816(acc[mt][np * 2 + 0], al[mt], bh[np][0], bh[np][1]);
                mma16816(acc[mt][np * 2 + 1], al[mt], bh[np][2], bh[np][3]);
            }
#pragma unroll
        for (int np = 0; np < 4; np++)
#pragma unroll
            for (int mt = 0; mt < 2; mt++) {
                mma16816(acc[mt][np * 2 + 0], ah[mt], bl[np][0], bl[np][1]);
                mma16816(acc[mt][np * 2 + 1], ah[mt], bl[np][2], bl[np][3]);
            }

        int stn = (st + 1 == 3) ? 0 : st + 1;
        if (c + 1 < NC) sts(stn, (c + 1) & 1);   // write stage (c+1)%3 from buffer (c+1)%2
        st = stn;
    }

    // ---- epilogue: fragment rows g / g+8; cols wn + nj*8 + 2*t4 + {0,1}
#pragma unroll
    for (int mt = 0; mt < 2; mt++) {
        int gr0 = row0 + wm + mt * 16 + g;
        int gr1 = gr0 + 8;
        bool a0 = gr0 < cnt, a1 = gr1 < cnt;
        int tok0 = 0, tok1 = 0; float gt0 = 0.f, gt1 = 0.f;
        if (MODE == 1) {
            if (a0) { tok0 = g_tok[e * NTOK + gr0]; gt0 = g_gate[e * NTOK + gr0]; }
            if (a1) { tok1 = g_tok[e * NTOK + gr1]; gt1 = g_gate[e * NTOK + gr1]; }
        }
#pragma unroll
        for (int nj = 0; nj < 8; nj++) {
            int cloc = wn + nj * 8 + 2 * t4;
            float b0v = s_bias[cloc], b1v = s_bias[cloc + 1];
            if (MODE == 0) {
                size_t o0 = (size_t)gr0 * KHID + col0 + cloc;
                size_t o1 = (size_t)gr1 * KHID + col0 + cloc;
                if (a0) {
                    g_H[o0]     = gelu_erf(acc[mt][nj][0] + b0v);
                    g_H[o0 + 1] = gelu_erf(acc[mt][nj][1] + b1v);
                }
                if (a1) {
                    g_H[o1]     = gelu_erf(acc[mt][nj][2] + b0v);
                    g_H[o1 + 1] = gelu_erf(acc[mt][nj][3] + b1v);
                }
            } else {
                int cb = col0 + cloc;
                if (a0) {
                    float* op = out + (size_t)tok0 * KDIM + cb;
                    op[0] += gt0 * expf(acc[mt][nj][0] + b0v);
                    op[1] += gt0 * expf(acc[mt][nj][1] + b1v);
                }
                if (a1) {
                    float* op = out + (size_t)tok1 * KDIM + cb;
                    op[0] += gt1 * expf(acc[mt][nj][2] + b0v);
                    op[1] += gt1 * expf(acc[mt][nj][3] + b1v);
                }
            }
        }
    }
}

// ---------------------------------------------------------------------------
__global__ void finalize_kernel(float* __restrict__ out, int n) {
    int i = blockIdx.x * blockDim.x + threadIdx.x;
    if (i < n) {
        float v = out[i];
        out[i] = logf(v == 0.0f ? 2.2204460492503131e-16f : v);
    }
}

// ---------------------------------------------------------------------------
extern "C" void kernel_launch(void* const* d_in, const int* in_sizes, int n_in,
                              void* d_out, int out_size) {
    const float* x  = (const float*)d_in[0];
    const float* wg = (const float*)d_in[1];
    const float* W1 = (const float*)d_in[2];
    const float* b1 = (const float*)d_in[3];
    const float* W2 = (const float*)d_in[4];
    const float* b2 = (const float*)d_in[5];
    float* out = (float*)d_out;

    cudaMemsetAsync(out, 0, (size_t)NTOK * KDIM * sizeof(float), 0);
    zero_counts_kernel<<<1, 32>>>();
    gating_kernel<<<(NTOK * 32 + 255) / 256, 256>>>(x, wg);

    for (int e = 0; e < NEXP; e++) {
        dim3 g1(KHID / 128, NTOK / 128);   // (24, 128)
        moe_mma_kernel<0><<<g1, 256>>>(x, W1, b1, e, out);
        dim3 g2(KDIM / 128, NTOK / 128);   // (6, 128)
        moe_mma_kernel<1><<<g2, 256>>>(g_H, W2, b2, e, out);
    }

    finalize_kernel<<<(NTOK * KDIM + 255) / 256, 256>>>(out, NTOK * KDIM);
}

// round 13
// speedup vs baseline: 1.2422x; 1.2422x over previous
#include <cuda_runtime.h>
#include <cuda_bf16.h>
#include <math.h>
#include <stdint.h>

#define NTOK 16384
#define KDIM 768
#define KHID 3072
#define NEXP 5

// ---------------- device scratch (static, allocation-free) ----------------
__device__ int   g_count[NEXP];
__device__ int   g_tok[NEXP * NTOK];
__device__ float g_gate[NEXP * NTOK];
__device__ float g_H[(size_t)NTOK * KHID];   // fp32 hidden scratch

// ---------------- helpers ----------------
__device__ __forceinline__ uint32_t smem_u32(const void* p) {
    uint32_t a;
    asm("{ .reg .u64 t; cvta.to.shared.u64 t, %1; cvt.u32.u64 %0, t; }" : "=r"(a) : "l"(p));
    return a;
}
__device__ __forceinline__ void mma16816(float (&c)[4], const uint32_t (&a)[4],
                                         uint32_t b0, uint32_t b1) {
    asm volatile("mma.sync.aligned.m16n8k16.row.col.f32.bf16.bf16.f32 "
                 "{%0,%1,%2,%3}, {%4,%5,%6,%7}, {%8,%9}, {%0,%1,%2,%3};"
                 : "+f"(c[0]), "+f"(c[1]), "+f"(c[2]), "+f"(c[3])
                 : "r"(a[0]), "r"(a[1]), "r"(a[2]), "r"(a[3]), "r"(b0), "r"(b1));
}
__device__ __forceinline__ void ldsm4(uint32_t (&d)[4], uint32_t addr) {
    asm volatile("ldmatrix.sync.aligned.m8n8.x4.shared.b16 {%0,%1,%2,%3}, [%4];"
                 : "=r"(d[0]), "=r"(d[1]), "=r"(d[2]), "=r"(d[3]) : "r"(addr));
}
__device__ __forceinline__ void ldsm4t(uint32_t (&d)[4], uint32_t addr) {
    asm volatile("ldmatrix.sync.aligned.m8n8.x4.trans.shared.b16 {%0,%1,%2,%3}, [%4];"
                 : "=r"(d[0]), "=r"(d[1]), "=r"(d[2]), "=r"(d[3]) : "r"(addr));
}
// split (fx, fy) -> packed bf16x2 hi (fx in low half) and bf16x2 lo (residual)
__device__ __forceinline__ void split2(float fx, float fy, uint32_t& hi, uint32_t& lo) {
    uint32_t h;
    asm("cvt.rn.bf16x2.f32 %0, %1, %2;" : "=r"(h) : "f"(fy), "f"(fx));
    float lx = fx - __uint_as_float(h << 16);
    float ly = fy - __uint_as_float(h & 0xffff0000u);
    asm("cvt.rn.bf16x2.f32 %0, %1, %2;" : "=r"(lo) : "f"(ly), "f"(lx));
    hi = h;
}
__device__ __forceinline__ float gelu_erf(float v) {
    return 0.5f * v * (1.0f + erff(v * 0.70710678118654752f));
}

// ---------------------------------------------------------------------------
__global__ void zero_counts_kernel() {
    if (threadIdx.x < NEXP) g_count[threadIdx.x] = 0;
}

__global__ void gating_kernel(const float* __restrict__ x, const float* __restrict__ wg) {
    int t = (blockIdx.x * blockDim.x + threadIdx.x) >> 5;
    int lane = threadIdx.x & 31;
    if (t >= NTOK) return;
    const float* xr = x + (size_t)t * KDIM;
    float p0 = 0.f, p1 = 0.f, p2 = 0.f, p3 = 0.f, p4 = 0.f;
    for (int k = lane; k < KDIM; k += 32) {
        float xv = xr[k];
        const float* w = wg + (size_t)k * NEXP;
        p0 += xv * w[0]; p1 += xv * w[1]; p2 += xv * w[2]; p3 += xv * w[3]; p4 += xv * w[4];
    }
#pragma unroll
    for (int o = 16; o > 0; o >>= 1) {
        p0 += __shfl_down_sync(0xffffffffu, p0, o);
        p1 += __shfl_down_sync(0xffffffffu, p1, o);
        p2 += __shfl_down_sync(0xffffffffu, p2, o);
        p3 += __shfl_down_sync(0xffffffffu, p3, o);
        p4 += __shfl_down_sync(0xffffffffu, p4, o);
    }
    if (lane == 0) {
        float v[NEXP] = {p0, p1, p2, p3, p4};
        int i0 = 0; float v0 = v[0];
#pragma unroll
        for (int e = 1; e < NEXP; e++) if (v[e] > v0) { v0 = v[e]; i0 = e; }
        int i1 = -1; float v1 = -3.4e38f;
#pragma unroll
        for (int e = 0; e < NEXP; e++) if (e != i0 && v[e] > v1) { v1 = v[e]; i1 = e; }
        float e1 = expf(v1 - v0);
        float s = 1.0f + e1;
        int q0 = atomicAdd(&g_count[i0], 1);
        g_tok[i0 * NTOK + q0] = t;  g_gate[i0 * NTOK + q0] = 1.0f / s;
        int q1 = atomicAdd(&g_count[i1], 1);
        g_tok[i1 * NTOK + q1] = t;  g_gate[i1 * NTOK + q1] = e1 / s;
    }
}

// ---------------------------------------------------------------------------
// GEMM: 128x128 CTA tile, 256 threads, 8 warps (4x2), warp tile 32x64.
// Pre-split fp32 -> bf16 hi/lo at STS into ldmatrix-friendly SMEM, 2-stage
// double buffer. __launch_bounds__(256, 2): regs capped at 128 so TWO CTAs
// co-reside per SM (4 warps/SMSP) -> one CTA's MMA burst covers the other's
// LDSM/barrier shadow.
#define CKE 16
#define ASTR 80
#define BSTR 528
#define A_STAGE (128 * ASTR)   // 10240 B
#define B_STAGE (16 * BSTR)    // 8448 B

// MODE 0 (fc1): A = gathered x rows [*,768], B = W1[e] [768,3072]; epi: g_H = gelu(acc+b1)
// MODE 1 (fc2): A = g_H [*,3072],          B = W2[e] [3072,768]; epi: out[tok] += gate*exp(acc+b2)
template <int MODE>
__global__ __launch_bounds__(256, 2)
void moe_mma_kernel(const float* __restrict__ x, const float* __restrict__ W,
                    const float* __restrict__ bias, int e, float* __restrict__ out) {
    int cnt = g_count[e];
    int row0 = blockIdx.y * 128;
    if (row0 >= cnt) return;
    int col0 = blockIdx.x * 128;

    const int KE = (MODE == 0) ? KDIM : KHID;   // reduction length
    const int NB = (MODE == 0) ? KHID : KDIM;   // output width (B row stride)

    __shared__ __align__(16) char sAbuf[2 * A_STAGE];
    __shared__ __align__(16) char sBbuf[2 * B_STAGE];
    __shared__ float s_bias[128];

    uint32_t Abase = smem_u32(sAbuf);
    uint32_t Bbase = smem_u32(sBbuf);

    int tid = threadIdx.x, wid = tid >> 5, lane = tid & 31;
    int wm = (wid & 3) * 32, wn = (wid >> 2) * 64;   // 4x2 warp grid, 32x64 tiles
    int g = lane >> 2, t4 = lane & 3;

    if (tid < 128) s_bias[tid] = bias[(size_t)e * NB + col0 + tid];

    // ---- per-lane ldmatrix base addresses (within stage 0) ----
    int mi = lane >> 3, rr = lane & 7;
    uint32_t aAddr = Abase + (uint32_t)((wm + ((mi & 1) << 3) + rr) * ASTR + ((mi >> 1) << 4));
    uint32_t bAddr = Bbase + (uint32_t)((((mi & 1) << 3) + rr) * BSTR + (wn + ((mi >> 1) << 3)) * 2);

    // ---- A loader: thread -> quad q (k 4q..4q+3), rows r0 and r0+64 ----
    int q = tid & 3, r0 = tid >> 2;
    const float *aSrc0, *aSrc1;
    if (MODE == 0) {
        int ga0 = row0 + r0, ga1 = row0 + r0 + 64;
        int tok0 = g_tok[e * NTOK + (ga0 < cnt ? ga0 : row0)];
        int tok1 = g_tok[e * NTOK + (ga1 < cnt ? ga1 : row0)];
        aSrc0 = x + (size_t)tok0 * KDIM + q * 4;
        aSrc1 = x + (size_t)tok1 * KDIM + q * 4;
    } else {
        aSrc0 = g_H + (size_t)(row0 + r0) * KHID + q * 4;       // rows >= cnt: finite garbage
        aSrc1 = g_H + (size_t)(row0 + r0 + 64) * KHID + q * 4;
    }
    // ---- B loader: thread -> k-row kr, n segment seg (8 cols) ----
    int kr = tid >> 4, seg = tid & 15;
    const float* bSrc = W + (size_t)e * KDIM * KHID + (size_t)kr * NB + col0 + seg * 8;

    float4 va0, va1, vb0, vb1;
    auto ldg = [&](int c) {
        va0 = *(const float4*)(aSrc0 + c * CKE);
        va1 = *(const float4*)(aSrc1 + c * CKE);
        const float* bp = bSrc + (size_t)c * CKE * NB;
        vb0 = *(const float4*)bp;
        vb1 = *(const float4*)(bp + 4);
    };
    auto sts = [&](int s) {
        char* Ab = sAbuf + s * A_STAGE;
        char* Bb = sBbuf + s * B_STAGE;
        uint32_t h0, l0, h1, l1, h2, l2, h3, l3;
        split2(va0.x, va0.y, h0, l0); split2(va0.z, va0.w, h1, l1);
        *(uint2*)(Ab + r0 * ASTR + q * 8)      = make_uint2(h0, h1);
        *(uint2*)(Ab + r0 * ASTR + 32 + q * 8) = make_uint2(l0, l1);
        split2(va1.x, va1.y, h0, l0); split2(va1.z, va1.w, h1, l1);
        *(uint2*)(Ab + (r0 + 64) * ASTR + q * 8)      = make_uint2(h0, h1);
        *(uint2*)(Ab + (r0 + 64) * ASTR + 32 + q * 8) = make_uint2(l0, l1);
        split2(vb0.x, vb0.y, h0, l0); split2(vb0.z, vb0.w, h1, l1);
        split2(vb1.x, vb1.y, h2, l2); split2(vb1.z, vb1.w, h3, l3);
        *(uint4*)(Bb + kr * BSTR + seg * 16)       = make_uint4(h0, h1, h2, h3);
        *(uint4*)(Bb + kr * BSTR + 256 + seg * 16) = make_uint4(l0, l1, l2, l3);
    };

    float acc[2][8][4];
#pragma unroll
    for (int i = 0; i < 2; i++)
#pragma unroll
        for (int j = 0; j < 8; j++)
#pragma unroll
            for (int k = 0; k < 4; k++) acc[i][j][k] = 0.f;

    const int NC = KE / CKE;
    ldg(0);
    sts(0);

    for (int c = 0; c < NC; c++) {
        __syncthreads();
        if (c + 1 < NC) ldg(c + 1);

        uint32_t stA = aAddr + (c & 1) * A_STAGE;
        uint32_t stB = bAddr + (c & 1) * B_STAGE;

        uint32_t ah[2][4], al[2][4];
#pragma unroll
        for (int mt = 0; mt < 2; mt++) {
            ldsm4(ah[mt], stA + mt * (16 * ASTR));
            ldsm4(al[mt], stA + mt * (16 * ASTR) + 32);
        }
#pragma unroll
        for (int np = 0; np < 4; np++) {
            uint32_t bh[4], bl[4];
            ldsm4t(bh, stB + np * 32);
            ldsm4t(bl, stB + np * 32 + 256);
#pragma unroll
            for (int mt = 0; mt < 2; mt++) {
                mma16816(acc[mt][np * 2 + 0], ah[mt], bh[0], bh[1]);
                mma16816(acc[mt][np * 2 + 1], ah[mt], bh[2], bh[3]);
                mma16816(acc[mt][np * 2 + 0], al[mt], bh[0], bh[1]);
                mma16816(acc[mt][np * 2 + 1], al[mt], bh[2], bh[3]);
                mma16816(acc[mt][np * 2 + 0], ah[mt], bl[0], bl[1]);
                mma16816(acc[mt][np * 2 + 1], ah[mt], bl[2], bl[3]);
            }
        }
        if (c + 1 < NC) sts((c + 1) & 1);
    }

    // ---- epilogue: fragment rows g / g+8; cols wn + nj*8 + 2*t4 + {0,1}
#pragma unroll
    for (int mt = 0; mt < 2; mt++) {
        int gr0 = row0 + wm + mt * 16 + g;
        int gr1 = gr0 + 8;
        bool a0 = gr0 < cnt, a1 = gr1 < cnt;
        int tok0 = 0, tok1 = 0; float gt0 = 0.f, gt1 = 0.f;
        if (MODE == 1) {
            if (a0) { tok0 = g_tok[e * NTOK + gr0]; gt0 = g_gate[e * NTOK + gr0]; }
            if (a1) { tok1 = g_tok[e * NTOK + gr1]; gt1 = g_gate[e * NTOK + gr1]; }
        }
#pragma unroll
        for (int nj = 0; nj < 8; nj++) {
            int cloc = wn + nj * 8 + 2 * t4;
            float b0v = s_bias[cloc], b1v = s_bias[cloc + 1];
            if (MODE == 0) {
                size_t o0 = (size_t)gr0 * KHID + col0 + cloc;
                size_t o1 = (size_t)gr1 * KHID + col0 + cloc;
                if (a0) {
                    g_H[o0]     = gelu_erf(acc[mt][nj][0] + b0v);
                    g_H[o0 + 1] = gelu_erf(acc[mt][nj][1] + b1v);
                }
                if (a1) {
                    g_H[o1]     = gelu_erf(acc[mt][nj][2] + b0v);
                    g_H[o1 + 1] = gelu_erf(acc[mt][nj][3] + b1v);
                }
            } else {
                int cb = col0 + cloc;
                if (a0) {
                    float* op = out + (size_t)tok0 * KDIM + cb;
                    op[0] += gt0 * expf(acc[mt][nj][0] + b0v);
                    op[1] += gt0 * expf(acc[mt][nj][1] + b1v);
                }
                if (a1) {
                    float* op = out + (size_t)tok1 * KDIM + cb;
                    op[0] += gt1 * expf(acc[mt][nj][2] + b0v);
                    op[1] += gt1 * expf(acc[mt][nj][3] + b1v);
                }
            }
        }
    }
}

// ---------------------------------------------------------------------------
__global__ void finalize_kernel(float* __restrict__ out, int n) {
    int i = blockIdx.x * blockDim.x + threadIdx.x;
    if (i < n) {
        float v = out[i];
        out[i] = logf(v == 0.0f ? 2.2204460492503131e-16f : v);
    }
}

// ---------------------------------------------------------------------------
extern "C" void kernel_launch(void* const* d_in, const int* in_sizes, int n_in,
                              void* d_out, int out_size) {
    const float* x  = (const float*)d_in[0];
    const float* wg = (const float*)d_in[1];
    const float* W1 = (const float*)d_in[2];
    const float* b1 = (const float*)d_in[3];
    const float* W2 = (const float*)d_in[4];
    const float* b2 = (const float*)d_in[5];
    float* out = (float*)d_out;

    cudaMemsetAsync(out, 0, (size_t)NTOK * KDIM * sizeof(float), 0);
    zero_counts_kernel<<<1, 32>>>();
    gating_kernel<<<(NTOK * 32 + 255) / 256, 256>>>(x, wg);

    for (int e = 0; e < NEXP; e++) {
        dim3 g1(KHID / 128, NTOK / 128);   // (24, 128)
        moe_mma_kernel<0><<<g1, 256>>>(x, W1, b1, e, out);
        dim3 g2(KDIM / 128, NTOK / 128);   // (6, 128)
        moe_mma_kernel<1><<<g2, 256>>>(g_H, W2, b2, e, out);
    }

    finalize_kernel<<<(NTOK * KDIM + 255) / 256, 256>>>(out, NTOK * KDIM);
}

// round 14
// speedup vs baseline: 1.7679x; 1.4233x over previous
#include <cuda_runtime.h>
#include <cuda_bf16.h>
#include <math.h>
#include <stdint.h>

#define NTOK 16384
#define KDIM 768
#define KHID 3072
#define NEXP 5
#define TOTROWS (2 * NTOK)   // sum of expert counts == 2*NTOK exactly

// ---------------- device scratch (static, allocation-free) ----------------
__device__ int   g_count[NEXP];
__device__ int   g_prefix[NEXP];
__device__ int   g_tok[NEXP * NTOK];
__device__ float g_gate[NEXP * NTOK];
__device__ int   g_tslot[2 * NTOK];                    // per token: (e<<20)|pos, 2 slots
__device__ float g_H[(size_t)TOTROWS * KHID];          // hidden scratch, prefix layout
__device__ float g_Y[(size_t)TOTROWS * KDIM];          // per-(expert,pos) gate*exp(y)

// ---------------- helpers ----------------
__device__ __forceinline__ uint32_t smem_u32(const void* p) {
    uint32_t a;
    asm("{ .reg .u64 t; cvta.to.shared.u64 t, %1; cvt.u32.u64 %0, t; }" : "=r"(a) : "l"(p));
    return a;
}
__device__ __forceinline__ void mma16816(float (&c)[4], const uint32_t (&a)[4],
                                         uint32_t b0, uint32_t b1) {
    asm volatile("mma.sync.aligned.m16n8k16.row.col.f32.bf16.bf16.f32 "
                 "{%0,%1,%2,%3}, {%4,%5,%6,%7}, {%8,%9}, {%0,%1,%2,%3};"
                 : "+f"(c[0]), "+f"(c[1]), "+f"(c[2]), "+f"(c[3])
                 : "r"(a[0]), "r"(a[1]), "r"(a[2]), "r"(a[3]), "r"(b0), "r"(b1));
}
__device__ __forceinline__ void ldsm4(uint32_t (&d)[4], uint32_t addr) {
    asm volatile("ldmatrix.sync.aligned.m8n8.x4.shared.b16 {%0,%1,%2,%3}, [%4];"
                 : "=r"(d[0]), "=r"(d[1]), "=r"(d[2]), "=r"(d[3]) : "r"(addr));
}
__device__ __forceinline__ void ldsm4t(uint32_t (&d)[4], uint32_t addr) {
    asm volatile("ldmatrix.sync.aligned.m8n8.x4.trans.shared.b16 {%0,%1,%2,%3}, [%4];"
                 : "=r"(d[0]), "=r"(d[1]), "=r"(d[2]), "=r"(d[3]) : "r"(addr));
}
// split (fx, fy) -> packed bf16x2 hi (fx in low half) and bf16x2 lo (residual)
__device__ __forceinline__ void split2(float fx, float fy, uint32_t& hi, uint32_t& lo) {
    uint32_t h;
    asm("cvt.rn.bf16x2.f32 %0, %1, %2;" : "=r"(h) : "f"(fy), "f"(fx));
    float lx = fx - __uint_as_float(h << 16);
    float ly = fy - __uint_as_float(h & 0xffff0000u);
    asm("cvt.rn.bf16x2.f32 %0, %1, %2;" : "=r"(lo) : "f"(ly), "f"(lx));
    hi = h;
}
__device__ __forceinline__ float gelu_erf(float v) {
    return 0.5f * v * (1.0f + erff(v * 0.70710678118654752f));
}

// ---------------------------------------------------------------------------
__global__ void zero_counts_kernel() {
    if (threadIdx.x < NEXP) g_count[threadIdx.x] = 0;
}

__global__ void prefix_kernel() {
    if (threadIdx.x == 0) {
        int s = 0;
        for (int e = 0; e < NEXP; e++) { g_prefix[e] = s; s += g_count[e]; }
    }
}

__global__ void gating_kernel(const float* __restrict__ x, const float* __restrict__ wg) {
    int t = (blockIdx.x * blockDim.x + threadIdx.x) >> 5;
    int lane = threadIdx.x & 31;
    if (t >= NTOK) return;
    const float* xr = x + (size_t)t * KDIM;
    float p0 = 0.f, p1 = 0.f, p2 = 0.f, p3 = 0.f, p4 = 0.f;
    for (int k = lane; k < KDIM; k += 32) {
        float xv = xr[k];
        const float* w = wg + (size_t)k * NEXP;
        p0 += xv * w[0]; p1 += xv * w[1]; p2 += xv * w[2]; p3 += xv * w[3]; p4 += xv * w[4];
    }
#pragma unroll
    for (int o = 16; o > 0; o >>= 1) {
        p0 += __shfl_down_sync(0xffffffffu, p0, o);
        p1 += __shfl_down_sync(0xffffffffu, p1, o);
        p2 += __shfl_down_sync(0xffffffffu, p2, o);
        p3 += __shfl_down_sync(0xffffffffu, p3, o);
        p4 += __shfl_down_sync(0xffffffffu, p4, o);
    }
    if (lane == 0) {
        float v[NEXP] = {p0, p1, p2, p3, p4};
        int i0 = 0; float v0 = v[0];
#pragma unroll
        for (int e = 1; e < NEXP; e++) if (v[e] > v0) { v0 = v[e]; i0 = e; }
        int i1 = -1; float v1 = -3.4e38f;
#pragma unroll
        for (int e = 0; e < NEXP; e++) if (e != i0 && v[e] > v1) { v1 = v[e]; i1 = e; }
        float e1 = expf(v1 - v0);
        float s = 1.0f + e1;
        int q0 = atomicAdd(&g_count[i0], 1);
        g_tok[i0 * NTOK + q0] = t;  g_gate[i0 * NTOK + q0] = 1.0f / s;
        int q1 = atomicAdd(&g_count[i1], 1);
        g_tok[i1 * NTOK + q1] = t;  g_gate[i1 * NTOK + q1] = e1 / s;
        g_tslot[2 * t + 0] = (i0 << 20) | q0;
        g_tslot[2 * t + 1] = (i1 << 20) | q1;
    }
}

// ---------------------------------------------------------------------------
// GEMM: 128x128 CTA tile, 256 threads, 8 warps (4x2), warp tile 32x64.
// ALL EXPERTS IN ONE LAUNCH (blockIdx.z = expert) -> wave pooling kills tail
// quantization. Pre-split fp32 -> bf16 hi/lo at STS, ldmatrix fragments,
// 2-stage double buffer, 2 CTAs/SM.
#define CKE 16
#define ASTR 80
#define BSTR 528
#define A_STAGE (128 * ASTR)   // 10240 B
#define B_STAGE (16 * BSTR)    // 8448 B

// MODE 0 (fc1): A = gathered x rows, B = W1[e] [768,3072]; epi: g_H[prefix+r] = gelu(acc+b1)
// MODE 1 (fc2): A = g_H[prefix+r],  B = W2[e] [3072,768]; epi: g_Y[prefix+r] = gate*exp(acc+b2)
template <int MODE>
__global__ __launch_bounds__(256, 2)
void moe_mma_kernel(const float* __restrict__ x, const float* __restrict__ W,
                    const float* __restrict__ bias) {
    int e = blockIdx.z;
    int cnt = g_count[e];
    int row0 = blockIdx.y * 128;
    if (row0 >= cnt) return;
    int col0 = blockIdx.x * 128;
    int hb = g_prefix[e];

    const int KE = (MODE == 0) ? KDIM : KHID;   // reduction length
    const int NB = (MODE == 0) ? KHID : KDIM;   // output width (B row stride)

    __shared__ __align__(16) char sAbuf[2 * A_STAGE];
    __shared__ __align__(16) char sBbuf[2 * B_STAGE];
    __shared__ float s_bias[128];

    uint32_t Abase = smem_u32(sAbuf);
    uint32_t Bbase = smem_u32(sBbuf);

    int tid = threadIdx.x, wid = tid >> 5, lane = tid & 31;
    int wm = (wid & 3) * 32, wn = (wid >> 2) * 64;   // 4x2 warp grid, 32x64 tiles
    int g = lane >> 2, t4 = lane & 3;

    if (tid < 128) s_bias[tid] = bias[(size_t)e * NB + col0 + tid];

    // ---- per-lane ldmatrix base addresses (within stage 0) ----
    int mi = lane >> 3, rr = lane & 7;
    uint32_t aAddr = Abase + (uint32_t)((wm + ((mi & 1) << 3) + rr) * ASTR + ((mi >> 1) << 4));
    uint32_t bAddr = Bbase + (uint32_t)((((mi & 1) << 3) + rr) * BSTR + (wn + ((mi >> 1) << 3)) * 2);

    // ---- A loader: thread -> quad q (k 4q..4q+3), rows r0 and r0+64 ----
    int q = tid & 3, r0 = tid >> 2;
    const float *aSrc0, *aSrc1;
    if (MODE == 0) {
        int ga0 = row0 + r0, ga1 = row0 + r0 + 64;
        int tok0 = g_tok[e * NTOK + (ga0 < cnt ? ga0 : row0)];
        int tok1 = g_tok[e * NTOK + (ga1 < cnt ? ga1 : row0)];
        aSrc0 = x + (size_t)tok0 * KDIM + q * 4;
        aSrc1 = x + (size_t)tok1 * KDIM + q * 4;
    } else {
        aSrc0 = g_H + (size_t)(hb + row0 + r0) * KHID + q * 4;        // rows >= cnt: finite garbage
        aSrc1 = g_H + (size_t)(hb + row0 + r0 + 64) * KHID + q * 4;
    }
    // ---- B loader: thread -> k-row kr, n segment seg (8 cols) ----
    int kr = tid >> 4, seg = tid & 15;
    const float* bSrc = W + (size_t)e * KDIM * KHID + (size_t)kr * NB + col0 + seg * 8;

    float4 va0, va1, vb0, vb1;
    auto ldg = [&](int c) {
        va0 = *(const float4*)(aSrc0 + c * CKE);
        va1 = *(const float4*)(aSrc1 + c * CKE);
        const float* bp = bSrc + (size_t)c * CKE * NB;
        vb0 = *(const float4*)bp;
        vb1 = *(const float4*)(bp + 4);
    };
    auto sts = [&](int s) {
        char* Ab = sAbuf + s * A_STAGE;
        char* Bb = sBbuf + s * B_STAGE;
        uint32_t h0, l0, h1, l1, h2, l2, h3, l3;
        split2(va0.x, va0.y, h0, l0); split2(va0.z, va0.w, h1, l1);
        *(uint2*)(Ab + r0 * ASTR + q * 8)      = make_uint2(h0, h1);
        *(uint2*)(Ab + r0 * ASTR + 32 + q * 8) = make_uint2(l0, l1);
        split2(va1.x, va1.y, h0, l0); split2(va1.z, va1.w, h1, l1);
        *(uint2*)(Ab + (r0 + 64) * ASTR + q * 8)      = make_uint2(h0, h1);
        *(uint2*)(Ab + (r0 + 64) * ASTR + 32 + q * 8) = make_uint2(l0, l1);
        split2(vb0.x, vb0.y, h0, l0); split2(vb0.z, vb0.w, h1, l1);
        split2(vb1.x, vb1.y, h2, l2); split2(vb1.z, vb1.w, h3, l3);
        *(uint4*)(Bb + kr * BSTR + seg * 16)       = make_uint4(h0, h1, h2, h3);
        *(uint4*)(Bb + kr * BSTR + 256 + seg * 16) = make_uint4(l0, l1, l2, l3);
    };

    float acc[2][8][4];
#pragma unroll
    for (int i = 0; i < 2; i++)
#pragma unroll
        for (int j = 0; j < 8; j++)
#pragma unroll
            for (int k = 0; k < 4; k++) acc[i][j][k] = 0.f;

    const int NC = KE / CKE;
    ldg(0);
    sts(0);

    for (int c = 0; c < NC; c++) {
        __syncthreads();
        if (c + 1 < NC) ldg(c + 1);

        uint32_t stA = aAddr + (c & 1) * A_STAGE;
        uint32_t stB = bAddr + (c & 1) * B_STAGE;

        uint32_t ah[2][4], al[2][4];
#pragma unroll
        for (int mt = 0; mt < 2; mt++) {
            ldsm4(ah[mt], stA + mt * (16 * ASTR));
            ldsm4(al[mt], stA + mt * (16 * ASTR) + 32);
        }
#pragma unroll
        for (int np = 0; np < 4; np++) {
            uint32_t bh[4], bl[4];
            ldsm4t(bh, stB + np * 32);
            ldsm4t(bl, stB + np * 32 + 256);
#pragma unroll
            for (int mt = 0; mt < 2; mt++) {
                mma16816(acc[mt][np * 2 + 0], ah[mt], bh[0], bh[1]);
                mma16816(acc[mt][np * 2 + 1], ah[mt], bh[2], bh[3]);
                mma16816(acc[mt][np * 2 + 0], al[mt], bh[0], bh[1]);
                mma16816(acc[mt][np * 2 + 1], al[mt], bh[2], bh[3]);
                mma16816(acc[mt][np * 2 + 0], ah[mt], bl[0], bl[1]);
                mma16816(acc[mt][np * 2 + 1], ah[mt], bl[2], bl[3]);
            }
        }
        if (c + 1 < NC) sts((c + 1) & 1);
    }

    // ---- epilogue: fragment rows g / g+8; cols wn + nj*8 + 2*t4 + {0,1}
#pragma unroll
    for (int mt = 0; mt < 2; mt++) {
        int gr0 = row0 + wm + mt * 16 + g;
        int gr1 = gr0 + 8;
        bool a0 = gr0 < cnt, a1 = gr1 < cnt;
        float gt0 = 0.f, gt1 = 0.f;
        if (MODE == 1) {
            if (a0) gt0 = g_gate[e * NTOK + gr0];
            if (a1) gt1 = g_gate[e * NTOK + gr1];
        }
#pragma unroll
        for (int nj = 0; nj < 8; nj++) {
            int cloc = wn + nj * 8 + 2 * t4;
            float b0v = s_bias[cloc], b1v = s_bias[cloc + 1];
            if (MODE == 0) {
                size_t o0 = (size_t)(hb + gr0) * KHID + col0 + cloc;
                size_t o1 = (size_t)(hb + gr1) * KHID + col0 + cloc;
                if (a0) {
                    g_H[o0]     = gelu_erf(acc[mt][nj][0] + b0v);
                    g_H[o0 + 1] = gelu_erf(acc[mt][nj][1] + b1v);
                }
                if (a1) {
                    g_H[o1]     = gelu_erf(acc[mt][nj][2] + b0v);
                    g_H[o1 + 1] = gelu_erf(acc[mt][nj][3] + b1v);
                }
            } else {
                size_t o0 = (size_t)(hb + gr0) * KDIM + col0 + cloc;
                size_t o1 = (size_t)(hb + gr1) * KDIM + col0 + cloc;
                if (a0) {
                    g_Y[o0]     = gt0 * expf(acc[mt][nj][0] + b0v);
                    g_Y[o0 + 1] = gt0 * expf(acc[mt][nj][1] + b1v);
                }
                if (a1) {
                    g_Y[o1]     = gt1 * expf(acc[mt][nj][2] + b0v);
                    g_Y[o1 + 1] = gt1 * expf(acc[mt][nj][3] + b1v);
                }
            }
        }
    }
}

// ---------------------------------------------------------------------------
// out[t][c] = log( Y[slot0(t)][c] + Y[slot1(t)][c] ), eps-guarded.
__global__ void finalize_kernel(float* __restrict__ out) {
    int t = blockIdx.x;
    int c = threadIdx.x + blockIdx.y * 256;
    int s0 = g_tslot[2 * t], s1 = g_tslot[2 * t + 1];
    int r0 = g_prefix[s0 >> 20] + (s0 & 0xFFFFF);
    int r1 = g_prefix[s1 >> 20] + (s1 & 0xFFFFF);
    float v = g_Y[(size_t)r0 * KDIM + c] + g_Y[(size_t)r1 * KDIM + c];
    out[(size_t)t * KDIM + c] = logf(v == 0.0f ? 2.2204460492503131e-16f : v);
}

// ---------------------------------------------------------------------------
extern "C" void kernel_launch(void* const* d_in, const int* in_sizes, int n_in,
                              void* d_out, int out_size) {
    const float* x  = (const float*)d_in[0];
    const float* wg = (const float*)d_in[1];
    const float* W1 = (const float*)d_in[2];
    const float* b1 = (const float*)d_in[3];
    const float* W2 = (const float*)d_in[4];
    const float* b2 = (const float*)d_in[5];
    float* out = (float*)d_out;

    zero_counts_kernel<<<1, 32>>>();
    gating_kernel<<<(NTOK * 32 + 255) / 256, 256>>>(x, wg);
    prefix_kernel<<<1, 32>>>();

    dim3 gf1(KHID / 128, NTOK / 128, NEXP);   // (24, 128, 5)
    moe_mma_kernel<0><<<gf1, 256>>>(x, W1, b1);
    dim3 gf2(KDIM / 128, NTOK / 128, NEXP);   // (6, 128, 5)
    moe_mma_kernel<1><<<gf2, 256>>>(g_H, W2, b2);

    dim3 gfin(NTOK, KDIM / 256);              // (16384, 3)
    finalize_kernel<<<gfin, 256>>>(out);
}

// round 15
// speedup vs baseline: 2.5982x; 1.4697x over previous
#include <cuda_runtime.h>
#include <cuda_fp16.h>
#include <math.h>
#include <stdint.h>

#define NTOK 16384
#define KDIM 768
#define KHID 3072
#define NEXP 5
#define TOTROWS (2 * NTOK)

// ---------------- device scratch (static, allocation-free) ----------------
__device__ int   g_count[NEXP];
__device__ int   g_prefix[NEXP];
__device__ int   g_tok[NEXP * NTOK];
__device__ float g_gate[NEXP * NTOK];
__device__ int   g_tslot[2 * NTOK];                    // per token: (e<<20)|pos
__device__ float g_H[(size_t)TOTROWS * KHID];          // hidden scratch, prefix layout
__device__ float g_Y[(size_t)TOTROWS * KDIM];          // per-(expert,pos) gate*exp(y)

// ---------------- helpers ----------------
__device__ __forceinline__ uint32_t smem_u32(const void* p) {
    uint32_t a;
    asm("{ .reg .u64 t; cvta.to.shared.u64 t, %1; cvt.u32.u64 %0, t; }" : "=r"(a) : "l"(p));
    return a;
}
__device__ __forceinline__ void mma16816(float (&c)[4], const uint32_t (&a)[4],
                                         uint32_t b0, uint32_t b1) {
    asm volatile("mma.sync.aligned.m16n8k16.row.col.f32.f16.f16.f32 "
                 "{%0,%1,%2,%3}, {%4,%5,%6,%7}, {%8,%9}, {%0,%1,%2,%3};"
                 : "+f"(c[0]), "+f"(c[1]), "+f"(c[2]), "+f"(c[3])
                 : "r"(a[0]), "r"(a[1]), "r"(a[2]), "r"(a[3]), "r"(b0), "r"(b1));
}
__device__ __forceinline__ void ldsm4(uint32_t (&d)[4], uint32_t addr) {
    asm volatile("ldmatrix.sync.aligned.m8n8.x4.shared.b16 {%0,%1,%2,%3}, [%4];"
                 : "=r"(d[0]), "=r"(d[1]), "=r"(d[2]), "=r"(d[3]) : "r"(addr));
}
__device__ __forceinline__ void ldsm4t(uint32_t (&d)[4], uint32_t addr) {
    asm volatile("ldmatrix.sync.aligned.m8n8.x4.trans.shared.b16 {%0,%1,%2,%3}, [%4];"
                 : "=r"(d[0]), "=r"(d[1]), "=r"(d[2]), "=r"(d[3]) : "r"(addr));
}
// A split: (fx, fy) -> packed fp16x2 hi and fp16x2 lo (residual)
__device__ __forceinline__ void splitA(float fx, float fy, uint32_t& hi, uint32_t& lo) {
    __half hx = __float2half_rn(fx), hy = __float2half_rn(fy);
    float lx = fx - __half2float(hx);
    float ly = fy - __half2float(hy);
    __half2 H = __halves2half2(hx, hy);
    __half2 L = __halves2half2(__float2half_rn(lx), __float2half_rn(ly));
    hi = *reinterpret_cast<uint32_t*>(&H);
    lo = *reinterpret_cast<uint32_t*>(&L);
}
// B: fp16 hi only
__device__ __forceinline__ uint32_t packB(float fx, float fy) {
    uint32_t h;
    asm("cvt.rn.f16x2.f32 %0, %1, %2;" : "=r"(h) : "f"(fy), "f"(fx));
    return h;
}
__device__ __forceinline__ float gelu_erf(float v) {
    return 0.5f * v * (1.0f + erff(v * 0.70710678118654752f));
}

// ---------------------------------------------------------------------------
__global__ void zero_counts_kernel() {
    if (threadIdx.x < NEXP) g_count[threadIdx.x] = 0;
}

__global__ void prefix_kernel() {
    if (threadIdx.x == 0) {
        int s = 0;
        for (int e = 0; e < NEXP; e++) { g_prefix[e] = s; s += g_count[e]; }
    }
}

__global__ void gating_kernel(const float* __restrict__ x, const float* __restrict__ wg) {
    int t = (blockIdx.x * blockDim.x + threadIdx.x) >> 5;
    int lane = threadIdx.x & 31;
    if (t >= NTOK) return;
    const float* xr = x + (size_t)t * KDIM;
    float p0 = 0.f, p1 = 0.f, p2 = 0.f, p3 = 0.f, p4 = 0.f;
    for (int k = lane; k < KDIM; k += 32) {
        float xv = xr[k];
        const float* w = wg + (size_t)k * NEXP;
        p0 += xv * w[0]; p1 += xv * w[1]; p2 += xv * w[2]; p3 += xv * w[3]; p4 += xv * w[4];
    }
#pragma unroll
    for (int o = 16; o > 0; o >>= 1) {
        p0 += __shfl_down_sync(0xffffffffu, p0, o);
        p1 += __shfl_down_sync(0xffffffffu, p1, o);
        p2 += __shfl_down_sync(0xffffffffu, p2, o);
        p3 += __shfl_down_sync(0xffffffffu, p3, o);
        p4 += __shfl_down_sync(0xffffffffu, p4, o);
    }
    if (lane == 0) {
        float v[NEXP] = {p0, p1, p2, p3, p4};
        int i0 = 0; float v0 = v[0];
#pragma unroll
        for (int e = 1; e < NEXP; e++) if (v[e] > v0) { v0 = v[e]; i0 = e; }
        int i1 = -1; float v1 = -3.4e38f;
#pragma unroll
        for (int e = 0; e < NEXP; e++) if (e != i0 && v[e] > v1) { v1 = v[e]; i1 = e; }
        float e1 = expf(v1 - v0);
        float s = 1.0f + e1;
        int q0 = atomicAdd(&g_count[i0], 1);
        g_tok[i0 * NTOK + q0] = t;  g_gate[i0 * NTOK + q0] = 1.0f / s;
        int q1 = atomicAdd(&g_count[i1], 1);
        g_tok[i1 * NTOK + q1] = t;  g_gate[i1 * NTOK + q1] = e1 / s;
        g_tslot[2 * t + 0] = (i0 << 20) | q0;
        g_tslot[2 * t + 1] = (i1 << 20) | q1;
    }
}

// ---------------------------------------------------------------------------
// GEMM: 128x128 CTA tile, 256 threads, 8 warps (4x2), warp tile 32x64.
// fp16 2-term split: A = ah + al (fp16 pair), B = bh (fp16) only.
// dot = ah*bh + al*bh. All experts pooled in one launch (blockIdx.z).
#define CKE 16
#define ASTR 80     // A row: 32B hi + 32B lo + 16B pad
#define BSTR 272    // B k-row: 256B hi + 16B pad (stride%128=16 -> conflict-free ldsm)
#define A_STAGE (128 * ASTR)   // 10240 B
#define B_STAGE (16 * BSTR)    // 4352 B

// MODE 0 (fc1): A = gathered x rows, B = W1[e]; epi: g_H[prefix+r] = gelu(acc+b1)
// MODE 1 (fc2): A = g_H[prefix+r],  B = W2[e]; epi: g_Y[prefix+r] = gate*exp(acc+b2)
template <int MODE>
__global__ __launch_bounds__(256, 2)
void moe_mma_kernel(const float* __restrict__ x, const float* __restrict__ W,
                    const float* __restrict__ bias) {
    int e = blockIdx.z;
    int cnt = g_count[e];
    int row0 = blockIdx.y * 128;
    if (row0 >= cnt) return;
    int col0 = blockIdx.x * 128;
    int hb = g_prefix[e];

    const int KE = (MODE == 0) ? KDIM : KHID;
    const int NB = (MODE == 0) ? KHID : KDIM;

    __shared__ __align__(16) char sAbuf[2 * A_STAGE];
    __shared__ __align__(16) char sBbuf[2 * B_STAGE];
    __shared__ float s_bias[128];

    uint32_t Abase = smem_u32(sAbuf);
    uint32_t Bbase = smem_u32(sBbuf);

    int tid = threadIdx.x, wid = tid >> 5, lane = tid & 31;
    int wm = (wid & 3) * 32, wn = (wid >> 2) * 64;
    int g = lane >> 2, t4 = lane & 3;

    if (tid < 128) s_bias[tid] = bias[(size_t)e * NB + col0 + tid];

    int mi = lane >> 3, rr = lane & 7;
    uint32_t aAddr = Abase + (uint32_t)((wm + ((mi & 1) << 3) + rr) * ASTR + ((mi >> 1) << 4));
    uint32_t bAddr = Bbase + (uint32_t)((((mi & 1) << 3) + rr) * BSTR + (wn + ((mi >> 1) << 3)) * 2);

    // ---- A loader: thread -> quad q (k 4q..4q+3), rows r0 and r0+64 ----
    int q = tid & 3, r0 = tid >> 2;
    const float *aSrc0, *aSrc1;
    if (MODE == 0) {
        int ga0 = row0 + r0, ga1 = row0 + r0 + 64;
        int tok0 = g_tok[e * NTOK + (ga0 < cnt ? ga0 : row0)];
        int tok1 = g_tok[e * NTOK + (ga1 < cnt ? ga1 : row0)];
        aSrc0 = x + (size_t)tok0 * KDIM + q * 4;
        aSrc1 = x + (size_t)tok1 * KDIM + q * 4;
    } else {
        aSrc0 = g_H + (size_t)(hb + row0 + r0) * KHID + q * 4;
        aSrc1 = g_H + (size_t)(hb + row0 + r0 + 64) * KHID + q * 4;
    }
    // ---- B loader: thread -> k-row kr, n segment seg (8 cols) ----
    int kr = tid >> 4, seg = tid & 15;
    const float* bSrc = W + (size_t)e * KDIM * KHID + (size_t)kr * NB + col0 + seg * 8;

    float4 va0, va1, vb0, vb1;
    auto ldg = [&](int c) {
        va0 = *(const float4*)(aSrc0 + c * CKE);
        va1 = *(const float4*)(aSrc1 + c * CKE);
        const float* bp = bSrc + (size_t)c * CKE * NB;
        vb0 = *(const float4*)bp;
        vb1 = *(const float4*)(bp + 4);
    };
    auto sts = [&](int s) {
        char* Ab = sAbuf + s * A_STAGE;
        char* Bb = sBbuf + s * B_STAGE;
        uint32_t h0, l0, h1, l1;
        splitA(va0.x, va0.y, h0, l0); splitA(va0.z, va0.w, h1, l1);
        *(uint2*)(Ab + r0 * ASTR + q * 8)      = make_uint2(h0, h1);
        *(uint2*)(Ab + r0 * ASTR + 32 + q * 8) = make_uint2(l0, l1);
        splitA(va1.x, va1.y, h0, l0); splitA(va1.z, va1.w, h1, l1);
        *(uint2*)(Ab + (r0 + 64) * ASTR + q * 8)      = make_uint2(h0, h1);
        *(uint2*)(Ab + (r0 + 64) * ASTR + 32 + q * 8) = make_uint2(l0, l1);
        uint32_t b0 = packB(vb0.x, vb0.y), b1 = packB(vb0.z, vb0.w);
        uint32_t b2 = packB(vb1.x, vb1.y), b3 = packB(vb1.z, vb1.w);
        *(uint4*)(Bb + kr * BSTR + seg * 16) = make_uint4(b0, b1, b2, b3);
    };

    float acc[2][8][4];
#pragma unroll
    for (int i = 0; i < 2; i++)
#pragma unroll
        for (int j = 0; j < 8; j++)
#pragma unroll
            for (int k = 0; k < 4; k++) acc[i][j][k] = 0.f;

    const int NC = KE / CKE;
    ldg(0);
    sts(0);

    for (int c = 0; c < NC; c++) {
        __syncthreads();
        if (c + 1 < NC) ldg(c + 1);

        uint32_t stA = aAddr + (c & 1) * A_STAGE;
        uint32_t stB = bAddr + (c & 1) * B_STAGE;

        uint32_t ah[2][4], al[2][4];
#pragma unroll
        for (int mt = 0; mt < 2; mt++) {
            ldsm4(ah[mt], stA + mt * (16 * ASTR));
            ldsm4(al[mt], stA + mt * (16 * ASTR) + 32);
        }
#pragma unroll
        for (int np = 0; np < 4; np++) {
            uint32_t bh[4];
            ldsm4t(bh, stB + np * 32);
#pragma unroll
            for (int mt = 0; mt < 2; mt++) {
                mma16816(acc[mt][np * 2 + 0], ah[mt], bh[0], bh[1]);
                mma16816(acc[mt][np * 2 + 1], ah[mt], bh[2], bh[3]);
                mma16816(acc[mt][np * 2 + 0], al[mt], bh[0], bh[1]);
                mma16816(acc[mt][np * 2 + 1], al[mt], bh[2], bh[3]);
            }
        }
        if (c + 1 < NC) sts((c + 1) & 1);
    }

    // ---- epilogue: fragment rows g / g+8; cols wn + nj*8 + 2*t4 + {0,1}
#pragma unroll
    for (int mt = 0; mt < 2; mt++) {
        int gr0 = row0 + wm + mt * 16 + g;
        int gr1 = gr0 + 8;
        bool a0 = gr0 < cnt, a1 = gr1 < cnt;
        float gt0 = 0.f, gt1 = 0.f;
        if (MODE == 1) {
            if (a0) gt0 = g_gate[e * NTOK + gr0];
            if (a1) gt1 = g_gate[e * NTOK + gr1];
        }
#pragma unroll
        for (int nj = 0; nj < 8; nj++) {
            int cloc = wn + nj * 8 + 2 * t4;
            float b0v = s_bias[cloc], b1v = s_bias[cloc + 1];
            if (MODE == 0) {
                size_t o0 = (size_t)(hb + gr0) * KHID + col0 + cloc;
                size_t o1 = (size_t)(hb + gr1) * KHID + col0 + cloc;
                if (a0) {
                    g_H[o0]     = gelu_erf(acc[mt][nj][0] + b0v);
                    g_H[o0 + 1] = gelu_erf(acc[mt][nj][1] + b1v);
                }
                if (a1) {
                    g_H[o1]     = gelu_erf(acc[mt][nj][2] + b0v);
                    g_H[o1 + 1] = gelu_erf(acc[mt][nj][3] + b1v);
                }
            } else {
                size_t o0 = (size_t)(hb + gr0) * KDIM + col0 + cloc;
                size_t o1 = (size_t)(hb + gr1) * KDIM + col0 + cloc;
                if (a0) {
                    g_Y[o0]     = gt0 * expf(acc[mt][nj][0] + b0v);
                    g_Y[o0 + 1] = gt0 * expf(acc[mt][nj][1] + b1v);
                }
                if (a1) {
                    g_Y[o1]     = gt1 * expf(acc[mt][nj][2] + b0v);
                    g_Y[o1 + 1] = gt1 * expf(acc[mt][nj][3] + b1v);
                }
            }
        }
    }
}

// ---------------------------------------------------------------------------
__global__ void finalize_kernel(float* __restrict__ out) {
    int t = blockIdx.x;
    int c = threadIdx.x + blockIdx.y * 256;
    int s0 = g_tslot[2 * t], s1 = g_tslot[2 * t + 1];
    int r0 = g_prefix[s0 >> 20] + (s0 & 0xFFFFF);
    int r1 = g_prefix[s1 >> 20] + (s1 & 0xFFFFF);
    float v = g_Y[(size_t)r0 * KDIM + c] + g_Y[(size_t)r1 * KDIM + c];
    out[(size_t)t * KDIM + c] = logf(v == 0.0f ? 2.2204460492503131e-16f : v);
}

// ---------------------------------------------------------------------------
extern "C" void kernel_launch(void* const* d_in, const int* in_sizes, int n_in,
                              void* d_out, int out_size) {
    const float* x  = (const float*)d_in[0];
    const float* wg = (const float*)d_in[1];
    const float* W1 = (const float*)d_in[2];
    const float* b1 = (const float*)d_in[3];
    const float* W2 = (const float*)d_in[4];
    const float* b2 = (const float*)d_in[5];
    float* out = (float*)d_out;

    zero_counts_kernel<<<1, 32>>>();
    gating_kernel<<<(NTOK * 32 + 255) / 256, 256>>>(x, wg);
    prefix_kernel<<<1, 32>>>();

    dim3 gf1(KHID / 128, NTOK / 128, NEXP);   // (24, 128, 5)
    moe_mma_kernel<0><<<gf1, 256>>>(x, W1, b1);
    dim3 gf2(KDIM / 128, NTOK / 128, NEXP);   // (6, 128, 5)
    moe_mma_kernel<1><<<gf2, 256>>>(g_H, W2, b2);

    dim3 gfin(NTOK, KDIM / 256);              // (16384, 3)
    finalize_kernel<<<gfin, 256>>>(out);
}

// round 16
// speedup vs baseline: 2.9137x; 1.1214x over previous
#include <cuda_runtime.h>
#include <cuda_fp16.h>
#include <math.h>
#include <stdint.h>

#define NTOK 16384
#define KDIM 768
#define KHID 3072
#define NEXP 5
#define TOTROWS (2 * NTOK)

// ---------------- device scratch (static, allocation-free) ----------------
__device__ int   g_count[NEXP];
__device__ int   g_prefix[NEXP];
__device__ int   g_tok[NEXP * NTOK];
__device__ float g_gate[NEXP * NTOK];
__device__ int   g_tslot[2 * NTOK];                    // per token: (e<<20)|pos
__device__ float g_H[(size_t)TOTROWS * KHID];          // hidden scratch, prefix layout
__device__ float g_Y[(size_t)TOTROWS * KDIM];          // per-(expert,pos) gate*exp(y)

// ---------------- helpers ----------------
__device__ __forceinline__ uint32_t smem_u32(const void* p) {
    uint32_t a;
    asm("{ .reg .u64 t; cvta.to.shared.u64 t, %1; cvt.u32.u64 %0, t; }" : "=r"(a) : "l"(p));
    return a;
}
__device__ __forceinline__ void mma16816(float (&c)[4], const uint32_t (&a)[4],
                                         uint32_t b0, uint32_t b1) {
    asm volatile("mma.sync.aligned.m16n8k16.row.col.f32.f16.f16.f32 "
                 "{%0,%1,%2,%3}, {%4,%5,%6,%7}, {%8,%9}, {%0,%1,%2,%3};"
                 : "+f"(c[0]), "+f"(c[1]), "+f"(c[2]), "+f"(c[3])
                 : "r"(a[0]), "r"(a[1]), "r"(a[2]), "r"(a[3]), "r"(b0), "r"(b1));
}
__device__ __forceinline__ void ldsm4(uint32_t (&d)[4], uint32_t addr) {
    asm volatile("ldmatrix.sync.aligned.m8n8.x4.shared.b16 {%0,%1,%2,%3}, [%4];"
                 : "=r"(d[0]), "=r"(d[1]), "=r"(d[2]), "=r"(d[3]) : "r"(addr));
}
__device__ __forceinline__ void ldsm4t(uint32_t (&d)[4], uint32_t addr) {
    asm volatile("ldmatrix.sync.aligned.m8n8.x4.trans.shared.b16 {%0,%1,%2,%3}, [%4];"
                 : "=r"(d[0]), "=r"(d[1]), "=r"(d[2]), "=r"(d[3]) : "r"(addr));
}
// pack (fx, fy) -> fp16x2 (fx in low half)
__device__ __forceinline__ uint32_t pack16(float fx, float fy) {
    uint32_t h;
    asm("cvt.rn.f16x2.f32 %0, %1, %2;" : "=r"(h) : "f"(fy), "f"(fx));
    return h;
}
__device__ __forceinline__ float gelu_erf(float v) {
    return 0.5f * v * (1.0f + erff(v * 0.70710678118654752f));
}

// ---------------------------------------------------------------------------
__global__ void zero_counts_kernel() {
    if (threadIdx.x < NEXP) g_count[threadIdx.x] = 0;
}

__global__ void prefix_kernel() {
    if (threadIdx.x == 0) {
        int s = 0;
        for (int e = 0; e < NEXP; e++) { g_prefix[e] = s; s += g_count[e]; }
    }
}

__global__ void gating_kernel(const float* __restrict__ x, const float* __restrict__ wg) {
    int t = (blockIdx.x * blockDim.x + threadIdx.x) >> 5;
    int lane = threadIdx.x & 31;
    if (t >= NTOK) return;
    const float* xr = x + (size_t)t * KDIM;
    float p0 = 0.f, p1 = 0.f, p2 = 0.f, p3 = 0.f, p4 = 0.f;
    for (int k = lane; k < KDIM; k += 32) {
        float xv = xr[k];
        const float* w = wg + (size_t)k * NEXP;
        p0 += xv * w[0]; p1 += xv * w[1]; p2 += xv * w[2]; p3 += xv * w[3]; p4 += xv * w[4];
    }
#pragma unroll
    for (int o = 16; o > 0; o >>= 1) {
        p0 += __shfl_down_sync(0xffffffffu, p0, o);
        p1 += __shfl_down_sync(0xffffffffu, p1, o);
        p2 += __shfl_down_sync(0xffffffffu, p2, o);
        p3 += __shfl_down_sync(0xffffffffu, p3, o);
        p4 += __shfl_down_sync(0xffffffffu, p4, o);
    }
    if (lane == 0) {
        float v[NEXP] = {p0, p1, p2, p3, p4};
        int i0 = 0; float v0 = v[0];
#pragma unroll
        for (int e = 1; e < NEXP; e++) if (v[e] > v0) { v0 = v[e]; i0 = e; }
        int i1 = -1; float v1 = -3.4e38f;
#pragma unroll
        for (int e = 0; e < NEXP; e++) if (e != i0 && v[e] > v1) { v1 = v[e]; i1 = e; }
        float e1 = expf(v1 - v0);
        float s = 1.0f + e1;
        int q0 = atomicAdd(&g_count[i0], 1);
        g_tok[i0 * NTOK + q0] = t;  g_gate[i0 * NTOK + q0] = 1.0f / s;
        int q1 = atomicAdd(&g_count[i1], 1);
        g_tok[i1 * NTOK + q1] = t;  g_gate[i1 * NTOK + q1] = e1 / s;
        g_tslot[2 * t + 0] = (i0 << 20) | q0;
        g_tslot[2 * t + 1] = (i1 << 20) | q1;
    }
}

// ---------------------------------------------------------------------------
// GEMM: 128x128 CTA tile, 256 threads, 8 warps (4x2), warp tile 32x64.
// PURE fp16: A = fp16(A), B = fp16(B), single term. 16 MMAs + 6 LDSM per
// warp-chunk. All experts pooled in one launch (blockIdx.z).
#define CKE 16
#define ASTR 48     // A row: 32B fp16 + 16B pad (bank-quads 0,3,6,1,4,7,2,5)
#define BSTR 272    // B k-row: 256B fp16 + 16B pad
#define A_STAGE (128 * ASTR)   // 6144 B
#define B_STAGE (16 * BSTR)    // 4352 B

// MODE 0 (fc1): A = gathered x rows, B = W1[e]; epi: g_H[prefix+r] = gelu(acc+b1)
// MODE 1 (fc2): A = g_H[prefix+r],  B = W2[e]; epi: g_Y[prefix+r] = gate*exp(acc+b2)
template <int MODE>
__global__ __launch_bounds__(256, 2)
void moe_mma_kernel(const float* __restrict__ x, const float* __restrict__ W,
                    const float* __restrict__ bias) {
    int e = blockIdx.z;
    int cnt = g_count[e];
    int row0 = blockIdx.y * 128;
    if (row0 >= cnt) return;
    int col0 = blockIdx.x * 128;
    int hb = g_prefix[e];

    const int KE = (MODE == 0) ? KDIM : KHID;
    const int NB = (MODE == 0) ? KHID : KDIM;

    __shared__ __align__(16) char sAbuf[2 * A_STAGE];
    __shared__ __align__(16) char sBbuf[2 * B_STAGE];
    __shared__ float s_bias[128];

    uint32_t Abase = smem_u32(sAbuf);
    uint32_t Bbase = smem_u32(sBbuf);

    int tid = threadIdx.x, wid = tid >> 5, lane = tid & 31;
    int wm = (wid & 3) * 32, wn = (wid >> 2) * 64;
    int g = lane >> 2, t4 = lane & 3;

    if (tid < 128) s_bias[tid] = bias[(size_t)e * NB + col0 + tid];

    int mi = lane >> 3, rr = lane & 7;
    uint32_t aAddr = Abase + (uint32_t)((wm + ((mi & 1) << 3) + rr) * ASTR + ((mi >> 1) << 4));
    uint32_t bAddr = Bbase + (uint32_t)((((mi & 1) << 3) + rr) * BSTR + (wn + ((mi >> 1) << 3)) * 2);

    // ---- A loader: thread -> quad q (k 4q..4q+3), rows r0 and r0+64 ----
    int q = tid & 3, r0 = tid >> 2;
    const float *aSrc0, *aSrc1;
    if (MODE == 0) {
        int ga0 = row0 + r0, ga1 = row0 + r0 + 64;
        int tok0 = g_tok[e * NTOK + (ga0 < cnt ? ga0 : row0)];
        int tok1 = g_tok[e * NTOK + (ga1 < cnt ? ga1 : row0)];
        aSrc0 = x + (size_t)tok0 * KDIM + q * 4;
        aSrc1 = x + (size_t)tok1 * KDIM + q * 4;
    } else {
        aSrc0 = g_H + (size_t)(hb + row0 + r0) * KHID + q * 4;
        aSrc1 = g_H + (size_t)(hb + row0 + r0 + 64) * KHID + q * 4;
    }
    // ---- B loader: thread -> k-row kr, n segment seg (8 cols) ----
    int kr = tid >> 4, seg = tid & 15;
    const float* bSrc = W + (size_t)e * KDIM * KHID + (size_t)kr * NB + col0 + seg * 8;

    float4 va0, va1, vb0, vb1;
    auto ldg = [&](int c) {
        va0 = *(const float4*)(aSrc0 + c * CKE);
        va1 = *(const float4*)(aSrc1 + c * CKE);
        const float* bp = bSrc + (size_t)c * CKE * NB;
        vb0 = *(const float4*)bp;
        vb1 = *(const float4*)(bp + 4);
    };
    auto sts = [&](int s) {
        char* Ab = sAbuf + s * A_STAGE;
        char* Bb = sBbuf + s * B_STAGE;
        *(uint2*)(Ab + r0 * ASTR + q * 8) =
            make_uint2(pack16(va0.x, va0.y), pack16(va0.z, va0.w));
        *(uint2*)(Ab + (r0 + 64) * ASTR + q * 8) =
            make_uint2(pack16(va1.x, va1.y), pack16(va1.z, va1.w));
        *(uint4*)(Bb + kr * BSTR + seg * 16) =
            make_uint4(pack16(vb0.x, vb0.y), pack16(vb0.z, vb0.w),
                       pack16(vb1.x, vb1.y), pack16(vb1.z, vb1.w));
    };

    float acc[2][8][4];
#pragma unroll
    for (int i = 0; i < 2; i++)
#pragma unroll
        for (int j = 0; j < 8; j++)
#pragma unroll
            for (int k = 0; k < 4; k++) acc[i][j][k] = 0.f;

    const int NC = KE / CKE;
    ldg(0);
    sts(0);

    for (int c = 0; c < NC; c++) {
        __syncthreads();
        if (c + 1 < NC) ldg(c + 1);

        uint32_t stA = aAddr + (c & 1) * A_STAGE;
        uint32_t stB = bAddr + (c & 1) * B_STAGE;

        uint32_t ah[2][4];
        ldsm4(ah[0], stA);
        ldsm4(ah[1], stA + 16 * ASTR);
#pragma unroll
        for (int np = 0; np < 4; np++) {
            uint32_t bh[4];
            ldsm4t(bh, stB + np * 32);
#pragma unroll
            for (int mt = 0; mt < 2; mt++) {
                mma16816(acc[mt][np * 2 + 0], ah[mt], bh[0], bh[1]);
                mma16816(acc[mt][np * 2 + 1], ah[mt], bh[2], bh[3]);
            }
        }
        if (c + 1 < NC) sts((c + 1) & 1);
    }

    // ---- epilogue: fragment rows g / g+8; cols wn + nj*8 + 2*t4 + {0,1}
#pragma unroll
    for (int mt = 0; mt < 2; mt++) {
        int gr0 = row0 + wm + mt * 16 + g;
        int gr1 = gr0 + 8;
        bool a0 = gr0 < cnt, a1 = gr1 < cnt;
        float gt0 = 0.f, gt1 = 0.f;
        if (MODE == 1) {
            if (a0) gt0 = g_gate[e * NTOK + gr0];
            if (a1) gt1 = g_gate[e * NTOK + gr1];
        }
#pragma unroll
        for (int nj = 0; nj < 8; nj++) {
            int cloc = wn + nj * 8 + 2 * t4;
            float b0v = s_bias[cloc], b1v = s_bias[cloc + 1];
            if (MODE == 0) {
                size_t o0 = (size_t)(hb + gr0) * KHID + col0 + cloc;
                size_t o1 = (size_t)(hb + gr1) * KHID + col0 + cloc;
                if (a0) {
                    g_H[o0]     = gelu_erf(acc[mt][nj][0] + b0v);
                    g_H[o0 + 1] = gelu_erf(acc[mt][nj][1] + b1v);
                }
                if (a1) {
                    g_H[o1]     = gelu_erf(acc[mt][nj][2] + b0v);
                    g_H[o1 + 1] = gelu_erf(acc[mt][nj][3] + b1v);
                }
            } else {
                size_t o0 = (size_t)(hb + gr0) * KDIM + col0 + cloc;
                size_t o1 = (size_t)(hb + gr1) * KDIM + col0 + cloc;
                if (a0) {
                    g_Y[o0]     = gt0 * expf(acc[mt][nj][0] + b0v);
                    g_Y[o0 + 1] = gt0 * expf(acc[mt][nj][1] + b1v);
                }
                if (a1) {
                    g_Y[o1]     = gt1 * expf(acc[mt][nj][2] + b0v);
                    g_Y[o1 + 1] = gt1 * expf(acc[mt][nj][3] + b1v);
                }
            }
        }
    }
}

// ---------------------------------------------------------------------------
__global__ void finalize_kernel(float* __restrict__ out) {
    int t = blockIdx.x;
    int c = threadIdx.x + blockIdx.y * 256;
    int s0 = g_tslot[2 * t], s1 = g_tslot[2 * t + 1];
    int r0 = g_prefix[s0 >> 20] + (s0 & 0xFFFFF);
    int r1 = g_prefix[s1 >> 20] + (s1 & 0xFFFFF);
    float v = g_Y[(size_t)r0 * KDIM + c] + g_Y[(size_t)r1 * KDIM + c];
    out[(size_t)t * KDIM + c] = logf(v == 0.0f ? 2.2204460492503131e-16f : v);
}

// ---------------------------------------------------------------------------
extern "C" void kernel_launch(void* const* d_in, const int* in_sizes, int n_in,
                              void* d_out, int out_size) {
    const float* x  = (const float*)d_in[0];
    const float* wg = (const float*)d_in[1];
    const float* W1 = (const float*)d_in[2];
    const float* b1 = (const float*)d_in[3];
    const float* W2 = (const float*)d_in[4];
    const float* b2 = (const float*)d_in[5];
    float* out = (float*)d_out;

    zero_counts_kernel<<<1, 32>>>();
    gating_kernel<<<(NTOK * 32 + 255) / 256, 256>>>(x, wg);
    prefix_kernel<<<1, 32>>>();

    dim3 gf1(KHID / 128, NTOK / 128, NEXP);   // (24, 128, 5)
    moe_mma_kernel<0><<<gf1, 256>>>(x, W1, b1);
    dim3 gf2(KDIM / 128, NTOK / 128, NEXP);   // (6, 128, 5)
    moe_mma_kernel<1><<<gf2, 256>>>(g_H, W2, b2);

    dim3 gfin(NTOK, KDIM / 256);              // (16384, 3)
    finalize_kernel<<<gfin, 256>>>(out);
}